// round 6
// baseline (speedup 1.0000x reference)
#include <cuda_runtime.h>

#define EPSV 1e-4f
#define T_LEN 4096
#define DH 1024
#define C3 3072
#define TT 256          // timesteps per tile (8 per lane)
#define NTILE 16        // 4096 / 256
#define PITCH 260       // smem row pitch in floats: 16B-aligned, conflict-free (260%32==4)

__device__ __forceinline__ float sigmoid_f(float x) {
    // MUFU.EX2 + MUFU.RCP — exact enough for the compounding cumprod path
    return __fdividef(1.0f, 1.0f + __expf(-x));
}

__device__ __forceinline__ float tanh_fast(float x) {
    // HW MUFU.TANH (sm_75+). Non-compounding paths only.
    float y;
    asm("tanh.approx.f32 %0, %1;" : "=f"(y) : "f"(x));
    return y;
}

// Block: 256 threads = 8 warps, owns (batch b, channels d0..d0+7).
// Tile = 256 timesteps. Warp w computes channel d0+w; lane l owns timesteps
// 8l..8l+7 of the tile (sequential in-lane, one warp-scan per recurrence per
// tile, scalar carry across tiles). Loads/stores are float4, transposed
// through padded smem. Activations fg/kv computed on the LOAD side; output
// gate og never transposes (held in regs, applied at the deferred store).
// Output store of tile k is deferred to iteration k+1 -> 2 barriers/tile.
__global__ __launch_bounds__(256) void glru_scan_kernel(
    const float* __restrict__ x, float* __restrict__ out)
{
    const int b   = blockIdx.y;
    const int d0  = blockIdx.x * 8;
    const int tid = threadIdx.x;
    const int w   = tid >> 5;        // channel within group (compute mapping)
    const int l   = tid & 31;        // lane = 8-timestep segment
    const int tl  = tid >> 1;        // time row 0..127 (load/store mapping; +128 for 2nd half)
    const int cq  = (tid & 1) * 4;   // channel quad 0 or 4 (load/store mapping)

    __shared__ float s_in[2][8][PITCH];   // [0]=fg, [1]=kv   ([ch][t], padded)
    __shared__ float s_out[8][PITCH];     // tanh(y) (og applied at store)

    const float* pin = x + ((size_t)(b * T_LEN) + tl) * C3 + d0 + cq;
    float*      pout = out + ((size_t)(b * T_LEN) + tl) * DH + d0 + cq;
    const size_t half_in  = (size_t)128 * C3;
    const size_t half_out = (size_t)128 * DH;

    // Prefetch tile 0 (two 128-row halves x 3 columns)
    float4 r0a = *(const float4*)(pin);
    float4 r1a = *(const float4*)(pin + DH);
    float4 r2a = *(const float4*)(pin + 2 * DH);
    float4 r0b = *(const float4*)(pin + half_in);
    float4 r1b = *(const float4*)(pin + half_in + DH);
    float4 r2b = *(const float4*)(pin + half_in + 2 * DH);
    pin += (size_t)TT * C3;

    float og_prev[8];        // og of tile k-1 (store side), valid from k=1
    float a_carry = 1.0f;    // running cumprod carry
    float s_carry = 0.0f;    // running cumsum carry

    for (int k = 0; k < NTILE; ++k) {
        __syncthreads();   // prev s_in consumed AND prev s_out visible

        // Deferred output of tile k-1: readback tanh(y), apply held og
        float4 ova, ovb;
        if (k > 0) {
            ova.x = s_out[cq + 0][tl] * og_prev[0];
            ova.y = s_out[cq + 1][tl] * og_prev[1];
            ova.z = s_out[cq + 2][tl] * og_prev[2];
            ova.w = s_out[cq + 3][tl] * og_prev[3];
            ovb.x = s_out[cq + 0][tl + 128] * og_prev[4];
            ovb.y = s_out[cq + 1][tl + 128] * og_prev[5];
            ovb.z = s_out[cq + 2][tl + 128] * og_prev[6];
            ovb.w = s_out[cq + 3][tl + 128] * og_prev[7];
        }

        // Load-side activation compute + staging of tile k (fg, kv only)
        {
            const float vxi[8] = {r0a.x, r0a.y, r0a.z, r0a.w, r0b.x, r0b.y, r0b.z, r0b.w};
            const float vxg[8] = {r1a.x, r1a.y, r1a.z, r1a.w, r1b.x, r1b.y, r1b.z, r1b.w};
            #pragma unroll
            for (int j = 0; j < 8; ++j) {
                const int row = cq + (j & 3);
                const int col = tl + (j >> 2) * 128;
                float ig = sigmoid_f(vxg[j]);
                s_in[0][row][col] = 1.0f - ig;                 // fg
                s_in[1][row][col] = tanh_fast(vxi[j]) * ig;    // kv
            }
        }
        // og for tile k, held in registers until iteration k+1's store
        og_prev[0] = sigmoid_f(r2a.x);  og_prev[1] = sigmoid_f(r2a.y);
        og_prev[2] = sigmoid_f(r2a.z);  og_prev[3] = sigmoid_f(r2a.w);
        og_prev[4] = sigmoid_f(r2b.x);  og_prev[5] = sigmoid_f(r2b.y);
        og_prev[6] = sigmoid_f(r2b.z);  og_prev[7] = sigmoid_f(r2b.w);

        // Prefetch tile k+1 (overlaps compute below)
        if (k + 1 < NTILE) {
            r0a = *(const float4*)(pin);
            r1a = *(const float4*)(pin + DH);
            r2a = *(const float4*)(pin + 2 * DH);
            r0b = *(const float4*)(pin + half_in);
            r1b = *(const float4*)(pin + half_in + DH);
            r2b = *(const float4*)(pin + half_in + 2 * DH);
            pin += (size_t)TT * C3;
        }

        // Deferred coalesced store of tile k-1
        if (k > 0) {
            *(float4*)pout = ova;
            *(float4*)(pout + half_out) = ovb;
            pout += (size_t)TT * DH;
        }

        __syncthreads();   // s_in ready

        const float4 fa = *(const float4*)&s_in[0][w][8 * l];
        const float4 fb = *(const float4*)&s_in[0][w][8 * l + 4];
        const float4 va = *(const float4*)&s_in[1][w][8 * l];
        const float4 vb = *(const float4*)&s_in[1][w][8 * l + 4];
        const float fg[8] = {fa.x, fa.y, fa.z, fa.w, fb.x, fb.y, fb.z, fb.w};
        const float kv[8] = {va.x, va.y, va.z, va.w, vb.x, vb.y, vb.z, vb.w};

        // Lane-local inclusive cumprod of forget gates
        float pc[8];
        pc[0] = fg[0];
        #pragma unroll
        for (int j = 1; j < 8; ++j) pc[j] = pc[j - 1] * fg[j];

        // Warp inclusive scan (product) of lane totals
        float incP = pc[7];
        #pragma unroll
        for (int off = 1; off < 32; off <<= 1) {
            float v = __shfl_up_sync(0xffffffffu, incP, off);
            if (l >= off) incP *= v;
        }
        float exP = __shfl_up_sync(0xffffffffu, incP, 1);
        if (l == 0) exP = 1.0f;
        const float abase = a_carry * exP;

        // term_j = kv_j / (a_j + eps), lane-local inclusive cumsum
        float sc[8];
        sc[0] = __fdividef(kv[0], abase * pc[0] + EPSV);
        #pragma unroll
        for (int j = 1; j < 8; ++j)
            sc[j] = sc[j - 1] + __fdividef(kv[j], abase * pc[j] + EPSV);

        // Warp inclusive scan (sum) of lane totals
        float incS = sc[7];
        #pragma unroll
        for (int off = 1; off < 32; off <<= 1) {
            float v = __shfl_up_sync(0xffffffffu, incS, off);
            if (l >= off) incS += v;
        }
        float exS = __shfl_up_sync(0xffffffffu, incS, 1);
        if (l == 0) exS = 0.0f;
        const float sbase = s_carry + exS;

        // Stage tanh(y); og multiplied at store time
        float o[8];
        #pragma unroll
        for (int j = 0; j < 8; ++j)
            o[j] = tanh_fast(abase * pc[j] * (sbase + sc[j]));
        float4 oa = {o[0], o[1], o[2], o[3]};
        float4 ob = {o[4], o[5], o[6], o[7]};
        *(float4*)&s_out[w][8 * l]     = oa;
        *(float4*)&s_out[w][8 * l + 4] = ob;

        // Carry update from lane 31's inclusive totals
        a_carry *= __shfl_sync(0xffffffffu, incP, 31);
        s_carry += __shfl_sync(0xffffffffu, incS, 31);
    }

    // Epilogue: flush last tile's output
    __syncthreads();
    float4 ova, ovb;
    ova.x = s_out[cq + 0][tl] * og_prev[0];
    ova.y = s_out[cq + 1][tl] * og_prev[1];
    ova.z = s_out[cq + 2][tl] * og_prev[2];
    ova.w = s_out[cq + 3][tl] * og_prev[3];
    ovb.x = s_out[cq + 0][tl + 128] * og_prev[4];
    ovb.y = s_out[cq + 1][tl + 128] * og_prev[5];
    ovb.z = s_out[cq + 2][tl + 128] * og_prev[6];
    ovb.w = s_out[cq + 3][tl + 128] * og_prev[7];
    *(float4*)pout = ova;
    *(float4*)(pout + half_out) = ovb;
}

extern "C" void kernel_launch(void* const* d_in, const int* in_sizes, int n_in,
                              void* d_out, int out_size)
{
    const float* x = (const float*)d_in[0];
    float* out = (float*)d_out;
    dim3 grid(DH / 8, 8);   // 128 channel-groups x 8 batches = 1024 blocks
    glru_scan_kernel<<<grid, 256>>>(x, out);
}

// round 7
// speedup vs baseline: 1.2126x; 1.2126x over previous
#include <cuda_runtime.h>

#define EPSV 1e-4f
#define T_LEN 4096
#define DH 1024
#define C3 3072
#define TT 128          // timesteps per tile (4 per lane)
#define NTILE 32        // 4096 / 128
#define PITCH 132       // smem row pitch in floats: 16B-aligned, conflict-free

__device__ __forceinline__ float tanh_fast(float x) {
    // HW MUFU.TANH (sm_75+): 1 MUFU op. Measured contribution ~5e-6 rel_err.
    float y;
    asm("tanh.approx.f32 %0, %1;" : "=f"(y) : "f"(x));
    return y;
}

// Block: 256 threads = 8 warps, owns (batch b, channels d0..d0+7).
// Tile = 128 timesteps; warp w computes channel d0+w, lane l owns timesteps
// 4l..4l+3 (lane-local chains + one warp shfl-scan per recurrence per tile,
// scalar carry across tiles).
//
// Software pipeline, ONE barrier per tile (double-buffered s_in/s_out):
//   iter k:  sync | store tile k-1 (s_out[nxt]) | stage tile k+1 (s_in[nxt])
//            | prefetch tile k+2 | compute tile k (s_in[cur] -> s_out[cur])
// All activations use MUFU.TANH: sigma(x) = 0.5 + 0.5*tanh(x/2); the forget
// gate is its exact complement 0.5 - 0.5*tanh(x/2)  -> 5 MUFU ops/element.
__global__ __launch_bounds__(256) void glru_scan_kernel(
    const float* __restrict__ x, float* __restrict__ out)
{
    const int b   = blockIdx.y;
    const int d0  = blockIdx.x * 8;
    const int tid = threadIdx.x;
    const int w   = tid >> 5;        // channel within group (compute mapping)
    const int l   = tid & 31;        // lane = 4-timestep segment
    const int tl  = tid >> 1;        // time row 0..127 (load/store mapping)
    const int cq  = (tid & 1) * 4;   // channel quad 0 or 4 (load/store mapping)

    __shared__ float s_in[2][2][8][PITCH];  // [buf][fg/kv][ch][t]
    __shared__ float s_out[2][8][PITCH];    // [buf][ch][t], tanh(y)

    const float* pin = x + ((size_t)(b * T_LEN) + tl) * C3 + d0 + cq;
    float*      pout = out + ((size_t)(b * T_LEN) + tl) * DH + d0 + cq;

    float4 r0, r1, r2;
    float4 og[2];            // og of tile j lives in og[j&1]

    // ---- Prologue: load + stage tile 0 into buf 0, then prefetch tile 1
    r0 = *(const float4*)(pin);
    r1 = *(const float4*)(pin + DH);
    r2 = *(const float4*)(pin + 2 * DH);
    pin += (size_t)TT * C3;
    {
        const float vxi[4] = {r0.x, r0.y, r0.z, r0.w};
        const float vxg[4] = {r1.x, r1.y, r1.z, r1.w};
        #pragma unroll
        for (int j = 0; j < 4; ++j) {
            float t  = tanh_fast(0.5f * vxg[j]);
            float ig = fmaf(0.5f, t, 0.5f);
            s_in[0][0][cq + j][tl] = fmaf(-0.5f, t, 0.5f);        // fg
            s_in[0][1][cq + j][tl] = tanh_fast(vxi[j]) * ig;      // kv
        }
        og[0].x = fmaf(0.5f, tanh_fast(0.5f * r2.x), 0.5f);
        og[0].y = fmaf(0.5f, tanh_fast(0.5f * r2.y), 0.5f);
        og[0].z = fmaf(0.5f, tanh_fast(0.5f * r2.z), 0.5f);
        og[0].w = fmaf(0.5f, tanh_fast(0.5f * r2.w), 0.5f);
    }
    r0 = *(const float4*)(pin);
    r1 = *(const float4*)(pin + DH);
    r2 = *(const float4*)(pin + 2 * DH);
    pin += (size_t)TT * C3;

    float a_carry = 1.0f;
    float s_carry = 0.0f;

    for (int k = 0; k < NTILE; ++k) {
        const int cur = k & 1;
        const int nxt = cur ^ 1;
        __syncthreads();   // the ONLY barrier: covers all cross-buffer hazards

        // D: deferred store of tile k-1 (staged in s_out[nxt] last iteration)
        if (k > 0) {
            const float4 ogp = og[nxt];          // parity (k-1)&1 == nxt
            float4 ov;
            ov.x = s_out[nxt][cq + 0][tl] * ogp.x;
            ov.y = s_out[nxt][cq + 1][tl] * ogp.y;
            ov.z = s_out[nxt][cq + 2][tl] * ogp.z;
            ov.w = s_out[nxt][cq + 3][tl] * ogp.w;
            *(float4*)pout = ov;
            pout += (size_t)TT * DH;
        }

        // B: stage tile k+1 into s_in[nxt]; og[(k+1)&1] == og[nxt] (after D read)
        if (k + 1 < NTILE) {
            const float vxi[4] = {r0.x, r0.y, r0.z, r0.w};
            const float vxg[4] = {r1.x, r1.y, r1.z, r1.w};
            #pragma unroll
            for (int j = 0; j < 4; ++j) {
                float t  = tanh_fast(0.5f * vxg[j]);
                float ig = fmaf(0.5f, t, 0.5f);
                s_in[nxt][0][cq + j][tl] = fmaf(-0.5f, t, 0.5f);   // fg
                s_in[nxt][1][cq + j][tl] = tanh_fast(vxi[j]) * ig; // kv
            }
            og[nxt].x = fmaf(0.5f, tanh_fast(0.5f * r2.x), 0.5f);
            og[nxt].y = fmaf(0.5f, tanh_fast(0.5f * r2.y), 0.5f);
            og[nxt].z = fmaf(0.5f, tanh_fast(0.5f * r2.z), 0.5f);
            og[nxt].w = fmaf(0.5f, tanh_fast(0.5f * r2.w), 0.5f);
        }

        // C: prefetch tile k+2
        if (k + 2 < NTILE) {
            r0 = *(const float4*)(pin);
            r1 = *(const float4*)(pin + DH);
            r2 = *(const float4*)(pin + 2 * DH);
            pin += (size_t)TT * C3;
        }

        // A: compute tile k from s_in[cur] (staged before this iteration's barrier)
        const float4 f4 = *(const float4*)&s_in[cur][0][w][4 * l];
        const float4 v4 = *(const float4*)&s_in[cur][1][w][4 * l];

        // Lane-local inclusive cumprod of forget gates
        float pc[4];
        pc[0] = f4.x;
        pc[1] = pc[0] * f4.y;
        pc[2] = pc[1] * f4.z;
        pc[3] = pc[2] * f4.w;

        // Warp inclusive scan (product) of lane totals
        float incP = pc[3];
        #pragma unroll
        for (int off = 1; off < 32; off <<= 1) {
            float v = __shfl_up_sync(0xffffffffu, incP, off);
            if (l >= off) incP *= v;
        }
        float exP = __shfl_up_sync(0xffffffffu, incP, 1);
        if (l == 0) exP = 1.0f;
        const float abase = a_carry * exP;

        // term_j = kv_j / (a_j + eps), lane-local inclusive cumsum
        float sc[4];
        sc[0] = __fdividef(v4.x, fmaf(abase, pc[0], EPSV));
        sc[1] = sc[0] + __fdividef(v4.y, fmaf(abase, pc[1], EPSV));
        sc[2] = sc[1] + __fdividef(v4.z, fmaf(abase, pc[2], EPSV));
        sc[3] = sc[2] + __fdividef(v4.w, fmaf(abase, pc[3], EPSV));

        // Warp inclusive scan (sum) of lane totals
        float incS = sc[3];
        #pragma unroll
        for (int off = 1; off < 32; off <<= 1) {
            float v = __shfl_up_sync(0xffffffffu, incS, off);
            if (l >= off) incS += v;
        }
        float exS = __shfl_up_sync(0xffffffffu, incS, 1);
        if (l == 0) exS = 0.0f;
        const float sbase = s_carry + exS;

        // Stage tanh(y) into s_out[cur]; og applied at next iteration's store
        float4 o;
        o.x = tanh_fast(abase * pc[0] * (sbase + sc[0]));
        o.y = tanh_fast(abase * pc[1] * (sbase + sc[1]));
        o.z = tanh_fast(abase * pc[2] * (sbase + sc[2]));
        o.w = tanh_fast(abase * pc[3] * (sbase + sc[3]));
        *(float4*)&s_out[cur][w][4 * l] = o;

        // Carry update from lane 31's inclusive totals
        a_carry *= __shfl_sync(0xffffffffu, incP, 31);
        s_carry += __shfl_sync(0xffffffffu, incS, 31);
    }

    // Epilogue: flush tile 31 (buffer 1, og[1])
    __syncthreads();
    {
        const float4 ogp = og[1];
        float4 ov;
        ov.x = s_out[1][cq + 0][tl] * ogp.x;
        ov.y = s_out[1][cq + 1][tl] * ogp.y;
        ov.z = s_out[1][cq + 2][tl] * ogp.z;
        ov.w = s_out[1][cq + 3][tl] * ogp.w;
        *(float4*)pout = ov;
    }
}

extern "C" void kernel_launch(void* const* d_in, const int* in_sizes, int n_in,
                              void* d_out, int out_size)
{
    const float* x = (const float*)d_in[0];
    float* out = (float*)d_out;
    dim3 grid(DH / 8, 8);   // 128 channel-groups x 8 batches = 1024 blocks
    glru_scan_kernel<<<grid, 256>>>(x, out);
}